// round 1
// baseline (speedup 1.0000x reference)
#include <cuda_runtime.h>

#define HH 512
#define WW 512
#define NC 48
#define NP (HH*WW)
#define NQ 12  // 48 floats = 12 float4

// ---- scratch (static device globals: allocation-free, graph-safe) ----
__device__ float4 g_x1[NP*NQ];
__device__ float4 g_x2[NP*NQ];
__device__ float  g_s[NP];
__device__ float  g_aux[NP*12];   // A0'..A8' (masked, /dg), ha', hb', hc'

__device__ __forceinline__ const float* src_ptr(int sel, const float* ext) {
    return sel == 0 ? ext : (sel == 1 ? (const float*)g_x1 : (const float*)g_x2);
}
__device__ __forceinline__ float* dst_ptr(int sel, float* ext) {
    return sel == 0 ? ext : (sel == 1 ? (float*)g_x1 : (float*)g_x2);
}

// ---- K0: per-pixel stencil weights from Dt (periodic rolls), folded /dg and 0.5*hinv ----
__global__ void k_aux(const float* __restrict__ Dt, const float* __restrict__ dg,
                      const float* __restrict__ hinv) {
    int p = blockIdx.x * blockDim.x + threadIdx.x;
    if (p >= NP) return;
    int h = p >> 9, w = p & 511;
    int hm = (h - 1) & 511, hp = (h + 1) & 511;
    int wm = (w - 1) & 511, wp = (w + 1) & 511;
    // Dt split: comp0 = a, comp1 = c, comp2 = b
    #define DTA(hh,ww) Dt[(((hh)<<9)+(ww))*3+0]
    #define DTC(hh,ww) Dt[(((hh)<<9)+(ww))*3+1]
    #define DTB(hh,ww) Dt[(((hh)<<9)+(ww))*3+2]
    float a00 = DTA(h,w),  c00 = DTC(h,w),  b00 = DTB(h,w);
    float a_hm = DTA(hm,w), b_hm = DTB(hm,w);   // (h-1, w)
    float a_hp = DTA(hp,w), b_hp = DTB(hp,w);   // (h+1, w)
    float c_wm = DTC(h,wm), b_wm = DTB(h,wm);   // (h, w-1)
    float c_wp = DTC(h,wp), b_wp = DTB(h,wp);   // (h, w+1)
    float b_mm = DTB(hm,wm);                    // (h-1, w-1)
    float b_mp = DTB(hm,wp);                    // (h-1, w+1)
    float b_pm = DTB(hp,wm);                    // (h+1, w-1)
    float b_pp = DTB(hp,wp);                    // (h+1, w+1)
    #undef DTA
    #undef DTC
    #undef DTB
    float A0 = (fabsf(b_pm) - b_pm + fabsf(b00) - b00) * 0.25f;
    float A1 = (c_wm + c00 - fabsf(b_wm) - fabsf(b00)) * 0.5f;
    float A2 = (fabsf(b_mm) + b_mm + fabsf(b00) + b00) * 0.25f;
    float A3 = (a_hp + a00 - fabsf(b_hp) - fabsf(b00)) * 0.5f;
    float A4 = -(a_hp + 2.0f*a00 + a_hm) * 0.5f
               - (fabsf(b_pm) - b_pm + fabsf(b_mm) + b_mm) * 0.25f
               - (fabsf(b_pp) + b_pp + fabsf(b_mp) - b_mp) * 0.25f
               + (fabsf(b_hp) + fabsf(b_hm) + fabsf(b_wp) + fabsf(b_wm) + 2.0f*fabsf(b00)) * 0.5f
               - (c_wp + 2.0f*c00 + c_wm) * 0.5f;
    float A5 = (a_hm + a00 - fabsf(b_hm) - fabsf(b00)) * 0.5f;
    float A6 = (fabsf(b_pp) + b_pp + fabsf(b00) + b00) * 0.25f;
    float A7 = (c_wp + c00 - fabsf(b_wp) - fabsf(b00)) * 0.5f;
    float A8 = (fabsf(b_mp) - b_mp + fabsf(b00) - b00) * 0.25f;

    float inv_dg = 1.0f / dg[p];
    // zero-padding masks for the local conv (SAME, zero pad)
    float mhm = (h > 0)      ? 1.0f : 0.0f;
    float mhp = (h < HH - 1) ? 1.0f : 0.0f;
    float mwm = (w > 0)      ? 1.0f : 0.0f;
    float mwp = (w < WW - 1) ? 1.0f : 0.0f;

    float* A = g_aux + p * 12;
    A[0] = A0 * inv_dg * mhm * mwm;
    A[1] = A1 * inv_dg * mhm;
    A[2] = A2 * inv_dg * mhm * mwp;
    A[3] = A3 * inv_dg * mwm;
    A[4] = A4 * inv_dg;
    A[5] = A5 * inv_dg * mwp;
    A[6] = A6 * inv_dg * mhp * mwm;
    A[7] = A7 * inv_dg * mhp;
    A[8] = A8 * inv_dg * mhp * mwp;
    A[9]  = 0.5f * hinv[p*3+0];  // coeff for vx^2
    A[10] = 0.5f * hinv[p*3+1];  // coeff for vy^2
    A[11] =        hinv[p*3+2];  // coeff for vx*vy (2 * c * 0.5)
}

// ---- K1: s = max + log(sum exp(x - max)) per pixel (logp[c] = x[c] - s) ----
__global__ void __launch_bounds__(256) k_s(int ssel, const float* __restrict__ ext) {
    int p = blockIdx.x * blockDim.x + threadIdx.x;
    if (p >= NP) return;
    const float4* xp = (const float4*)src_ptr(ssel, ext) + (size_t)p * NQ;
    float4 v[NQ];
    float m = -3.402823466e38f;
    #pragma unroll
    for (int q = 0; q < NQ; q++) {
        v[q] = xp[q];
        m = fmaxf(m, fmaxf(fmaxf(v[q].x, v[q].y), fmaxf(v[q].z, v[q].w)));
    }
    float sum = 0.0f;
    #pragma unroll
    for (int q = 0; q < NQ; q++) {
        sum += __expf(v[q].x - m) + __expf(v[q].y - m)
             + __expf(v[q].z - m) + __expf(v[q].w - m);
    }
    g_s[p] = m + __logf(sum);
}

// ---- K2: one fused Euler step ----
__global__ void __launch_bounds__(128) k_step(int ssel, int dsel,
                                              const float* __restrict__ ext_in,
                                              float* __restrict__ ext_out) {
    int p = blockIdx.x * blockDim.x + threadIdx.x;
    if (p >= NP) return;
    const float* x = src_ptr(ssel, ext_in);
    float* xo = dst_ptr(dsel, ext_out);

    int h = p >> 9, w = p & 511;
    int hm = (h - 1) & 511, hp = (h + 1) & 511;
    int wm = (w - 1) & 511, wp = (w + 1) & 511;

    const float* A = g_aux + p * 12;
    float A0 = A[0], A1 = A[1], A2 = A[2], A3 = A[3], A4 = A[4];
    float A5 = A[5], A6 = A[6], A7 = A[7], A8 = A[8];
    float ha = A[9], hb = A[10], hc = A[11];

    float sc  = g_s[p];
    float dsx = g_s[(hp << 9) + w] - sc;   // periodic roll along H
    float dsy = g_s[(h << 9) + wp] - sc;   // periodic roll along W

    const float4* q_mm = (const float4*)x + (size_t)((hm << 9) + wm) * NQ;
    const float4* q_m0 = (const float4*)x + (size_t)((hm << 9) + w ) * NQ;
    const float4* q_mp = (const float4*)x + (size_t)((hm << 9) + wp) * NQ;
    const float4* q_0m = (const float4*)x + (size_t)((h  << 9) + wm) * NQ;
    const float4* q_00 = (const float4*)x + (size_t)p * NQ;
    const float4* q_0p = (const float4*)x + (size_t)((h  << 9) + wp) * NQ;
    const float4* q_pm = (const float4*)x + (size_t)((hp << 9) + wm) * NQ;
    const float4* q_p0 = (const float4*)x + (size_t)((hp << 9) + w ) * NQ;
    const float4* q_pp = (const float4*)x + (size_t)((hp << 9) + wp) * NQ;

    float4 val[NQ];
    float vsum = 0.0f;
    #pragma unroll
    for (int q = 0; q < NQ; q++) {
        float4 tmm = q_mm[q], tm0 = q_m0[q], tmp_ = q_mp[q];
        float4 t0m = q_0m[q], t00 = q_00[q], t0p  = q_0p[q];
        float4 tpm = q_pm[q], tp0 = q_p0[q], tpp  = q_pp[q];
        float4 r;
        #define DO(f) { \
            float acc = A4 * t00.f; \
            acc = fmaf(A0, tmm.f, acc);  acc = fmaf(A1, tm0.f, acc);  acc = fmaf(A2, tmp_.f, acc); \
            acc = fmaf(A3, t0m.f, acc);  acc = fmaf(A5, t0p.f, acc); \
            acc = fmaf(A6, tpm.f, acc);  acc = fmaf(A7, tp0.f, acc);  acc = fmaf(A8, tpp.f, acc); \
            float vx = (tp0.f - t00.f) - dsx; \
            float vy = (t0p.f - t00.f) - dsy; \
            acc = fmaf(fmaf(hc, vy, ha * vx), vx, acc); \
            acc = fmaf(hb, vy * vy, acc); \
            acc = fmaf(0.1f, t00.f, acc); \
            r.f = acc; vsum += acc; }
        DO(x) DO(y) DO(z) DO(w)
        #undef DO
        val[q] = r;
    }
    float mean = vsum * (1.0f / 48.0f);

    float4* o = (float4*)xo + (size_t)p * NQ;
    #pragma unroll
    for (int q = 0; q < NQ; q++) {
        float4 xc = q_00[q];  // L1 hit reload (cheaper than 48 more live regs)
        float4 r = val[q], oo;
        #define DO2(f) { \
            float t = r.f - mean; \
            t = fminf(fmaxf(t, -1e8f), 1e8f); \
            oo.f = fmaf(0.2f, t, xc.f); }
        DO2(x) DO2(y) DO2(z) DO2(w)
        #undef DO2
        o[q] = oo;
    }
}

extern "C" void kernel_launch(void* const* d_in, const int* in_sizes, int n_in,
                              void* d_out, int out_size) {
    const float* v    = (const float*)d_in[0];
    const float* Dt   = (const float*)d_in[1];
    const float* dg   = (const float*)d_in[2];
    const float* hinv = (const float*)d_in[3];
    float* out = (float*)d_out;

    k_aux<<<NP / 256, 256>>>(Dt, dg, hinv);

    // ping-pong: v -> g_x1 -> g_x2 -> g_x1 -> g_x2 -> d_out
    int dsel[5] = {1, 2, 1, 2, 0};
    int ssel = 0;
    for (int i = 0; i < 5; i++) {
        k_s<<<NP / 256, 256>>>(ssel, v);
        k_step<<<NP / 128, 128>>>(ssel, dsel[i], v, out);
        ssel = dsel[i];
    }
}